// round 6
// baseline (speedup 1.0000x reference)
#include <cuda_runtime.h>
#include <cuda_bf16.h>

#define MAX_N 100000
#define N_GRAPHS 64
#define FEAT 64
#define MAX_E 1600000

// ---------------- scratch (device globals; no allocations) ----------------
__device__ float g_h[MAX_N * FEAT];       // layer-1 output
__device__ float g_h2[MAX_N * FEAT];      // layer-2 output
__device__ int   g_deg[MAX_N];
__device__ int   g_rowstart[MAX_N + 1];
__device__ int   g_cursor[MAX_N];
__device__ int   g_srcs[MAX_E];
__device__ int   g_bsum[128];
__device__ int   g_boff[128];
__device__ float g_pooled[N_GRAPHS * FEAT];
__device__ int   g_ei64;
__device__ int   g_b64;

// ---------------- dtype detection (warp-parallel) ----------------
__global__ void detect_kernel(const void* ei, const void* batch, int nE, int nN) {
    int lane = threadIdx.x;
    const long long* p = (const long long*)ei;
    long long v = p[lane];
    int ok = (v >= 0 && v < (long long)nN);
    unsigned m = __ballot_sync(0xffffffffu, ok);
    int idx = nN / 2 - 1 - lane;
    long long bv = (idx >= 0) ? ((const long long*)batch)[idx] : 0;
    int bok = (bv >= 0 && bv < 64);
    unsigned bm = __ballot_sync(0xffffffffu, bok);
    if (lane == 0) {
        g_ei64 = (m == 0xffffffffu) ? 1 : 0;
        g_b64  = (bm == 0xffffffffu) ? 1 : 0;
    }
}

// ---------------- CSR build ----------------
__global__ void zero_deg_kernel(int nN) {
    int i = blockIdx.x * blockDim.x + threadIdx.x;
    if (i < nN) g_deg[i] = 0;
}

__global__ void hist_kernel(const void* __restrict__ ei_v, int nE) {
    int e = blockIdx.x * blockDim.x + threadIdx.x;
    if (e >= nE) return;
    int dst;
    if (g_ei64) dst = (int)((const long long*)ei_v)[(long long)nE + e];
    else        dst = ((const int*)ei_v)[nE + e];
    atomicAdd(&g_deg[dst], 1);
}

__global__ void scan_block_kernel(int nN) {
    __shared__ int wsum[8];
    __shared__ int woff[8];
    int blk = blockIdx.x, t = threadIdx.x;
    int base = blk * 1024 + t * 4;
    int v0 = (base + 0 < nN) ? g_deg[base + 0] : 0;
    int v1 = (base + 1 < nN) ? g_deg[base + 1] : 0;
    int v2 = (base + 2 < nN) ? g_deg[base + 2] : 0;
    int v3 = (base + 3 < nN) ? g_deg[base + 3] : 0;
    int i0 = v0, i1 = i0 + v1, i2 = i1 + v2, i3 = i2 + v3;
    int tot = i3;
    int lane = t & 31, w = t >> 5;
    int sc = tot;
    #pragma unroll
    for (int off = 1; off < 32; off <<= 1) {
        int n = __shfl_up_sync(0xffffffffu, sc, off);
        if (lane >= off) sc += n;
    }
    if (lane == 31) wsum[w] = sc;
    __syncthreads();
    if (t < 8) {
        int v = wsum[t];
        int s = v;
        #pragma unroll
        for (int off = 1; off < 8; off <<= 1) {
            int n = __shfl_up_sync(0xffu, s, off);
            if (t >= off) s += n;
        }
        woff[t] = s - v;
        if (t == 7) g_bsum[blk] = s;
    }
    __syncthreads();
    int excl = woff[w] + (sc - tot);
    if (base + 0 < nN) g_rowstart[base + 0] = excl;
    if (base + 1 < nN) g_rowstart[base + 1] = excl + i0;
    if (base + 2 < nN) g_rowstart[base + 2] = excl + i1;
    if (base + 3 < nN) g_rowstart[base + 3] = excl + i2;
}

__global__ void scan_tops_kernel(int nBlocks) {
    __shared__ int wsum[4];
    __shared__ int woff[4];
    int t = threadIdx.x;
    int v = (t < nBlocks) ? g_bsum[t] : 0;
    int lane = t & 31, w = t >> 5;
    int s = v;
    #pragma unroll
    for (int off = 1; off < 32; off <<= 1) {
        int n = __shfl_up_sync(0xffffffffu, s, off);
        if (lane >= off) s += n;
    }
    if (lane == 31) wsum[w] = s;
    __syncthreads();
    if (t < 4) {
        int vv = wsum[t];
        int ss = vv;
        #pragma unroll
        for (int off = 1; off < 4; off <<= 1) {
            int n = __shfl_up_sync(0xfu, ss, off);
            if (t >= off) ss += n;
        }
        woff[t] = ss - vv;
    }
    __syncthreads();
    if (t < nBlocks) g_boff[t] = (s - v) + woff[w];
}

__global__ void scan_add_kernel(int nN, int nE) {
    int i = blockIdx.x * blockDim.x + threadIdx.x;
    if (i < nN) {
        int s = g_rowstart[i] + g_boff[i >> 10];
        g_rowstart[i] = s;
        g_cursor[i] = s;
    }
    if (i == 0) g_rowstart[nN] = nE;
}

__global__ void fill_kernel(const void* __restrict__ ei_v, int nE) {
    int e = blockIdx.x * blockDim.x + threadIdx.x;
    if (e >= nE) return;
    int src, dst;
    if (g_ei64) {
        const long long* ei = (const long long*)ei_v;
        src = (int)ei[e];
        dst = (int)ei[(long long)nE + e];
    } else {
        const int* ei = (const int*)ei_v;
        src = ei[e];
        dst = ei[nE + e];
    }
    int pos = atomicAdd(&g_cursor[dst], 1);
    g_srcs[pos] = src;
}

// ---------------- fused layer: gather-mean + GEMM + relu ------------------
// Phase A: each of 8 warps gathers 8 nodes' neighbor means into sIn[. ][0:16]
//          (lanes 0-15 = neighbor i, lanes 16-31 = neighbor i+1, float4 chunks)
//          + cooperative load of X tile into sIn[.][16:32) and weights.
// Phase B: 64x64 scalar-FFMA GEMM over fused K=128, relu, store.
// Blocks at staggered phases overlap gather memory with GEMM compute.
__global__ void fused_layer(const float* __restrict__ feat,   // neighbor rows
                            const float* __restrict__ Xin,    // root rows (same data)
                            const float* __restrict__ Wrel,
                            const float* __restrict__ Wroot,
                            const float* __restrict__ bias,
                            float* __restrict__ out,
                            int nRows) {
    __shared__ float4 sW[128][16];
    __shared__ float4 sIn[64][33];
    __shared__ float  sB[64];

    int tid = threadIdx.x;
    int rowBase = blockIdx.x * 64;
    int warp = tid >> 5;
    int lane = tid & 31;
    int half = lane >> 4;
    int c = lane & 15;

    // weights + bias
    #pragma unroll
    for (int i = tid; i < 2048; i += 256) {
        int k = i >> 4, j = i & 15;
        sW[k][j] = (k < 64) ? reinterpret_cast<const float4*>(Wrel)[k * 16 + j]
                            : reinterpret_cast<const float4*>(Wroot)[(k - 64) * 16 + j];
    }
    if (tid < 64) sB[tid] = bias[tid];

    // X tile -> sIn[r][16..31]
    #pragma unroll
    for (int i = tid; i < 1024; i += 256) {
        int r = i >> 4, q = i & 15;
        int row = rowBase + r;
        sIn[r][16 + q] = (row < nRows)
            ? reinterpret_cast<const float4*>(Xin)[row * 16 + q]
            : make_float4(0.f, 0.f, 0.f, 0.f);
    }

    // gather phase: warp w -> rows 8w .. 8w+7
    #pragma unroll
    for (int it = 0; it < 8; it++) {
        int r = warp * 8 + it;
        int node = rowBase + r;
        float4 acc = make_float4(0.f, 0.f, 0.f, 0.f);
        int deg = 0;
        if (node < nRows) {
            int s = g_rowstart[node];
            int e = g_rowstart[node + 1];
            deg = e - s;
            int i = s;
            // 8 neighbors per iter (4 per half) -> MLP 4 row-loads in flight
            for (; i + 8 <= e; i += 8) {
                int a0 = __ldg(&g_srcs[i + half]);
                int a1 = __ldg(&g_srcs[i + 2 + half]);
                int a2 = __ldg(&g_srcs[i + 4 + half]);
                int a3 = __ldg(&g_srcs[i + 6 + half]);
                float4 v0 = __ldg((const float4*)(feat + (size_t)a0 * FEAT) + c);
                float4 v1 = __ldg((const float4*)(feat + (size_t)a1 * FEAT) + c);
                float4 v2 = __ldg((const float4*)(feat + (size_t)a2 * FEAT) + c);
                float4 v3 = __ldg((const float4*)(feat + (size_t)a3 * FEAT) + c);
                acc.x += (v0.x + v1.x) + (v2.x + v3.x);
                acc.y += (v0.y + v1.y) + (v2.y + v3.y);
                acc.z += (v0.z + v1.z) + (v2.z + v3.z);
                acc.w += (v0.w + v1.w) + (v2.w + v3.w);
            }
            for (; i + 2 <= e; i += 2) {
                int a0 = __ldg(&g_srcs[i + half]);
                float4 v0 = __ldg((const float4*)(feat + (size_t)a0 * FEAT) + c);
                acc.x += v0.x; acc.y += v0.y; acc.z += v0.z; acc.w += v0.w;
            }
            if (i < e && half == 0) {
                int a0 = __ldg(&g_srcs[i]);
                float4 v0 = __ldg((const float4*)(feat + (size_t)a0 * FEAT) + c);
                acc.x += v0.x; acc.y += v0.y; acc.z += v0.z; acc.w += v0.w;
            }
        }
        acc.x += __shfl_down_sync(0xffffffffu, acc.x, 16);
        acc.y += __shfl_down_sync(0xffffffffu, acc.y, 16);
        acc.z += __shfl_down_sync(0xffffffffu, acc.z, 16);
        acc.w += __shfl_down_sync(0xffffffffu, acc.w, 16);
        if (half == 0) {
            float inv = 1.0f / fmaxf((float)deg, 1.0f);
            sIn[r][c] = make_float4(acc.x * inv, acc.y * inv, acc.z * inv, acc.w * inv);
        }
    }
    __syncthreads();

    // GEMM phase (proven scalar core)
    int tx = tid & 15;
    int ty = tid >> 4;
    float acc[4][4];
    #pragma unroll
    for (int i = 0; i < 4; i++)
        #pragma unroll
        for (int j = 0; j < 4; j++) acc[i][j] = 0.f;

    #pragma unroll 8
    for (int k4 = 0; k4 < 32; ++k4) {
        float4 a0 = sIn[ty      ][k4];
        float4 a1 = sIn[ty + 16][k4];
        float4 a2 = sIn[ty + 32][k4];
        float4 a3 = sIn[ty + 48][k4];
        float4 w0 = sW[4 * k4 + 0][tx];
        float4 w1 = sW[4 * k4 + 1][tx];
        float4 w2 = sW[4 * k4 + 2][tx];
        float4 w3 = sW[4 * k4 + 3][tx];
        float4 a[4] = {a0, a1, a2, a3};
        #pragma unroll
        for (int i = 0; i < 4; i++) {
            acc[i][0] += a[i].x * w0.x + a[i].y * w1.x + a[i].z * w2.x + a[i].w * w3.x;
            acc[i][1] += a[i].x * w0.y + a[i].y * w1.y + a[i].z * w2.y + a[i].w * w3.y;
            acc[i][2] += a[i].x * w0.z + a[i].y * w1.z + a[i].z * w2.z + a[i].w * w3.z;
            acc[i][3] += a[i].x * w0.w + a[i].y * w1.w + a[i].z * w2.w + a[i].w * w3.w;
        }
    }

    #pragma unroll
    for (int i = 0; i < 4; i++) {
        int row = rowBase + ty + 16 * i;
        if (row < nRows) {
            float4 o;
            o.x = fmaxf(acc[i][0] + sB[tx * 4 + 0], 0.f);
            o.y = fmaxf(acc[i][1] + sB[tx * 4 + 1], 0.f);
            o.z = fmaxf(acc[i][2] + sB[tx * 4 + 2], 0.f);
            o.w = fmaxf(acc[i][3] + sB[tx * 4 + 3], 0.f);
            reinterpret_cast<float4*>(out)[row * 16 + tx] = o;
        }
    }
}

// ---------------- global mean pool (reads g_h2) ----------------
__device__ __forceinline__ long long batch_at(const void* b, int i, int is64) {
    return is64 ? ((const long long*)b)[i] : (long long)((const int*)b)[i];
}

__global__ void pool_kernel(const void* __restrict__ batch, int nRows) {
    int g = blockIdx.x;
    int is64 = g_b64;
    int lo = 0, hi = nRows;
    while (lo < hi) { int m = (lo + hi) >> 1; if (batch_at(batch, m, is64) < g) lo = m + 1; else hi = m; }
    int start = lo;
    lo = 0; hi = nRows;
    while (lo < hi) { int m = (lo + hi) >> 1; if (batch_at(batch, m, is64) < g + 1) lo = m + 1; else hi = m; }
    int end = lo;

    int feat = threadIdx.x & 63;
    int rl   = threadIdx.x >> 6;
    float s = 0.f;
    for (int r = start + rl; r < end; r += 4)
        s += g_h2[(long long)r * FEAT + feat];

    __shared__ float sm[4][64];
    sm[rl][feat] = s;
    __syncthreads();
    if (rl == 0) {
        float tot = sm[0][feat] + sm[1][feat] + sm[2][feat] + sm[3][feat];
        g_pooled[g * FEAT + feat] = tot / fmaxf((float)(end - start), 1.0f);
    }
}

// ---------------- heads ----------------
__global__ void head_kernel(const float* __restrict__ Wh, const float* __restrict__ bh,
                            const float* __restrict__ Wc, const float* __restrict__ bc,
                            const float* __restrict__ Wo, const float* __restrict__ bo,
                            float* __restrict__ out) {
    __shared__ float sp[64 * 64];
    __shared__ float sh[64 * 64];
    int tid = threadIdx.x;

    for (int i = tid; i < 4096; i += 256) sp[i] = g_pooled[i];
    __syncthreads();

    for (int i = tid; i < 4096; i += 256) {
        int g = i >> 6, j = i & 63;
        float ah = bh[j], ac = bc[j];
        #pragma unroll 8
        for (int k = 0; k < 64; k++) {
            float p = sp[g * 64 + k];
            ah += p * Wh[k * 64 + j];
            ac += p * Wc[k * 64 + j];
        }
        sh[i] = ah;
        out[2048 + i] = ah;
        out[2048 + 4096 + i] = ac;
    }
    __syncthreads();

    int warp = tid >> 5, lane = tid & 31;
    for (int g = warp; g < 64; g += 8) {
        float z = bo[lane];
        #pragma unroll 8
        for (int k = 0; k < 64; k++)
            z += sh[g * 64 + k] * Wo[k * 32 + lane];
        float m = z;
        #pragma unroll
        for (int off = 16; off > 0; off >>= 1)
            m = fmaxf(m, __shfl_xor_sync(0xffffffffu, m, off));
        float s = expf(z - m);
        #pragma unroll
        for (int off = 16; off > 0; off >>= 1)
            s += __shfl_xor_sync(0xffffffffu, s, off);
        out[g * 32 + lane] = z - m - logf(s);
    }
}

// ---------------- launch ----------------
extern "C" void kernel_launch(void* const* d_in, const int* in_sizes, int n_in,
                              void* d_out, int out_size) {
    const float* x     = (const float*)d_in[0];
    const void*  ei    = d_in[1];
    const void*  batch = d_in[2];
    const float* W1    = (const float*)d_in[3];
    const float* root1 = (const float*)d_in[4];
    const float* b1    = (const float*)d_in[5];
    const float* W2    = (const float*)d_in[6];
    const float* root2 = (const float*)d_in[7];
    const float* b2    = (const float*)d_in[8];
    const float* Wh    = (const float*)d_in[9];
    const float* bh    = (const float*)d_in[10];
    const float* Wc    = (const float*)d_in[11];
    const float* bc    = (const float*)d_in[12];
    const float* Wo    = (const float*)d_in[13];
    const float* bo    = (const float*)d_in[14];

    int nN = in_sizes[0] / FEAT;   // 100000
    int nE = in_sizes[1] / 2;      // 1600000

    int eBlocks = (nE + 255) / 256;
    int nBlocks = (nN + 255) / 256;
    int scanBlocks = (nN + 1023) / 1024;
    int fusedBlocks = (nN + 63) / 64;

    float* h1 = nullptr; float* h2 = nullptr;
    cudaGetSymbolAddress((void**)&h1, g_h);
    cudaGetSymbolAddress((void**)&h2, g_h2);

    detect_kernel<<<1, 32>>>(ei, batch, nE, nN);

    // CSR build
    zero_deg_kernel<<<nBlocks, 256>>>(nN);
    hist_kernel<<<eBlocks, 256>>>(ei, nE);
    scan_block_kernel<<<scanBlocks, 256>>>(nN);
    scan_tops_kernel<<<1, 128>>>(scanBlocks);
    scan_add_kernel<<<nBlocks, 256>>>(nN, nE);
    fill_kernel<<<eBlocks, 256>>>(ei, nE);

    // fused layers (gather + GEMM + relu in one kernel)
    fused_layer<<<fusedBlocks, 256>>>(x,  x,  W1, root1, b1, h1, nN);
    fused_layer<<<fusedBlocks, 256>>>(h1, h1, W2, root2, b2, h2, nN);

    // pool + heads
    pool_kernel<<<N_GRAPHS, 256>>>(batch, nN);
    head_kernel<<<1, 256>>>(Wh, bh, Wc, bc, Wo, bo, (float*)d_out);
}

// round 7
// speedup vs baseline: 1.0985x; 1.0985x over previous
#include <cuda_runtime.h>
#include <cuda_bf16.h>

#define MAX_N 100000
#define N_GRAPHS 64
#define FEAT 64
#define MAX_E 1600000

// ---------------- scratch (device globals; no allocations) ----------------
__device__ float g_S[MAX_N * FEAT];       // aggregated (mean) neighbor features
__device__ float g_h[MAX_N * FEAT];       // layer output (reused in-place)
__device__ int   g_deg[MAX_N];
__device__ int   g_rowstart[MAX_N + 1];
__device__ int   g_cursor[MAX_N];
__device__ int   g_srcs[MAX_E];
__device__ int   g_bsum[128];
__device__ int   g_boff[128];
__device__ float g_pooled[N_GRAPHS * FEAT];
__device__ int   g_ei64;
__device__ int   g_b64;

// ---------------- dtype detection (warp-parallel) ----------------
__global__ void detect_kernel(const void* ei, const void* batch, int nE, int nN) {
    int lane = threadIdx.x;
    const long long* p = (const long long*)ei;
    long long v = p[lane];
    int ok = (v >= 0 && v < (long long)nN);
    unsigned m = __ballot_sync(0xffffffffu, ok);
    int idx = nN / 2 - 1 - lane;
    long long bv = (idx >= 0) ? ((const long long*)batch)[idx] : 0;
    int bok = (bv >= 0 && bv < 64);
    unsigned bm = __ballot_sync(0xffffffffu, bok);
    if (lane == 0) {
        g_ei64 = (m == 0xffffffffu) ? 1 : 0;
        g_b64  = (bm == 0xffffffffu) ? 1 : 0;
    }
}

// ---------------- CSR build ----------------
__global__ void zero_deg_kernel(int nN) {
    int i = blockIdx.x * blockDim.x + threadIdx.x;
    if (i < nN) g_deg[i] = 0;
}

__global__ void hist_kernel(const void* __restrict__ ei_v, int nE) {
    int e = blockIdx.x * blockDim.x + threadIdx.x;
    if (e >= nE) return;
    int dst;
    if (g_ei64) dst = (int)((const long long*)ei_v)[(long long)nE + e];
    else        dst = ((const int*)ei_v)[nE + e];
    atomicAdd(&g_deg[dst], 1);
}

__global__ void scan_block_kernel(int nN) {
    __shared__ int wsum[8];
    __shared__ int woff[8];
    int blk = blockIdx.x, t = threadIdx.x;
    int base = blk * 1024 + t * 4;
    int v0 = (base + 0 < nN) ? g_deg[base + 0] : 0;
    int v1 = (base + 1 < nN) ? g_deg[base + 1] : 0;
    int v2 = (base + 2 < nN) ? g_deg[base + 2] : 0;
    int v3 = (base + 3 < nN) ? g_deg[base + 3] : 0;
    int i0 = v0, i1 = i0 + v1, i2 = i1 + v2, i3 = i2 + v3;
    int tot = i3;
    int lane = t & 31, w = t >> 5;
    int sc = tot;
    #pragma unroll
    for (int off = 1; off < 32; off <<= 1) {
        int n = __shfl_up_sync(0xffffffffu, sc, off);
        if (lane >= off) sc += n;
    }
    if (lane == 31) wsum[w] = sc;
    __syncthreads();
    if (t < 8) {
        int v = wsum[t];
        int s = v;
        #pragma unroll
        for (int off = 1; off < 8; off <<= 1) {
            int n = __shfl_up_sync(0xffu, s, off);
            if (t >= off) s += n;
        }
        woff[t] = s - v;
        if (t == 7) g_bsum[blk] = s;
    }
    __syncthreads();
    int excl = woff[w] + (sc - tot);
    if (base + 0 < nN) g_rowstart[base + 0] = excl;
    if (base + 1 < nN) g_rowstart[base + 1] = excl + i0;
    if (base + 2 < nN) g_rowstart[base + 2] = excl + i1;
    if (base + 3 < nN) g_rowstart[base + 3] = excl + i2;
}

__global__ void scan_tops_kernel(int nBlocks) {
    __shared__ int wsum[4];
    __shared__ int woff[4];
    int t = threadIdx.x;
    int v = (t < nBlocks) ? g_bsum[t] : 0;
    int lane = t & 31, w = t >> 5;
    int s = v;
    #pragma unroll
    for (int off = 1; off < 32; off <<= 1) {
        int n = __shfl_up_sync(0xffffffffu, s, off);
        if (lane >= off) s += n;
    }
    if (lane == 31) wsum[w] = s;
    __syncthreads();
    if (t < 4) {
        int vv = wsum[t];
        int ss = vv;
        #pragma unroll
        for (int off = 1; off < 4; off <<= 1) {
            int n = __shfl_up_sync(0xfu, ss, off);
            if (t >= off) ss += n;
        }
        woff[t] = ss - vv;
    }
    __syncthreads();
    if (t < nBlocks) g_boff[t] = (s - v) + woff[w];
}

__global__ void scan_add_kernel(int nN, int nE) {
    int i = blockIdx.x * blockDim.x + threadIdx.x;
    if (i < nN) {
        int s = g_rowstart[i] + g_boff[i >> 10];
        g_rowstart[i] = s;
        g_cursor[i] = s;
    }
    if (i == 0) g_rowstart[nN] = nE;
}

__global__ void fill_kernel(const void* __restrict__ ei_v, int nE) {
    int e = blockIdx.x * blockDim.x + threadIdx.x;
    if (e >= nE) return;
    int src, dst;
    if (g_ei64) {
        const long long* ei = (const long long*)ei_v;
        src = (int)ei[e];
        dst = (int)ei[(long long)nE + e];
    } else {
        const int* ei = (const int*)ei_v;
        src = ei[e];
        dst = ei[nE + e];
    }
    int pos = atomicAdd(&g_cursor[dst], 1);
    g_srcs[pos] = src;
}

// ---------------- gather-mean v3: warp per node, shfl-broadcast indices ----
// One coalesced LDG.32 prefetches 32 indices per warp; row loads (32 lanes x
// float2 = full 256B row) are then issued back-to-back with NO dependent idx
// load in between. Unroll x4 => >=4 independent row loads in flight per warp.
__global__ void gather_kernel(const float* __restrict__ x, int nN, int fromH) {
    int gtid = blockIdx.x * blockDim.x + threadIdx.x;
    int node = gtid >> 5;
    int lane = gtid & 31;
    if (node >= nN) return;
    const float* base = fromH ? (const float*)g_h : x;
    int s = g_rowstart[node];
    int e = g_rowstart[node + 1];
    float ax = 0.f, ay = 0.f;

    for (int b = s; b < e; b += 32) {
        int cnt = min(32, e - b);
        int idxv = (lane < cnt) ? __ldg(&g_srcs[b + lane]) : 0;
        int j = 0;
        for (; j + 4 <= cnt; j += 4) {
            int a0 = __shfl_sync(0xffffffffu, idxv, j);
            int a1 = __shfl_sync(0xffffffffu, idxv, j + 1);
            int a2 = __shfl_sync(0xffffffffu, idxv, j + 2);
            int a3 = __shfl_sync(0xffffffffu, idxv, j + 3);
            float2 v0 = __ldg((const float2*)(base + (size_t)a0 * FEAT) + lane);
            float2 v1 = __ldg((const float2*)(base + (size_t)a1 * FEAT) + lane);
            float2 v2 = __ldg((const float2*)(base + (size_t)a2 * FEAT) + lane);
            float2 v3 = __ldg((const float2*)(base + (size_t)a3 * FEAT) + lane);
            ax += (v0.x + v1.x) + (v2.x + v3.x);
            ay += (v0.y + v1.y) + (v2.y + v3.y);
        }
        for (; j < cnt; j++) {
            int a0 = __shfl_sync(0xffffffffu, idxv, j);
            float2 v0 = __ldg((const float2*)(base + (size_t)a0 * FEAT) + lane);
            ax += v0.x; ay += v0.y;
        }
    }
    float inv = 1.0f / fmaxf((float)(e - s), 1.0f);
    reinterpret_cast<float2*>(g_S)[node * 32 + lane] = make_float2(ax * inv, ay * inv);
}

// ---------------- fused RGCN layer GEMM (proven scalar core) ----------
__global__ void rgcn_gemm(const float* __restrict__ Xin,
                          const float* __restrict__ Wrel,
                          const float* __restrict__ Wroot,
                          const float* __restrict__ bias,
                          int nRows, int xIsH) {
    const float* X = xIsH ? (const float*)g_h : Xin;
    __shared__ float4 sW[128][16];
    __shared__ float4 sIn[64][33];
    __shared__ float  sB[64];

    int tid = threadIdx.x;
    int rowBase = blockIdx.x * 64;

    #pragma unroll
    for (int i = tid; i < 2048; i += 256) {
        int k = i >> 4, j = i & 15;
        sW[k][j] = (k < 64) ? reinterpret_cast<const float4*>(Wrel)[k * 16 + j]
                            : reinterpret_cast<const float4*>(Wroot)[(k - 64) * 16 + j];
    }
    if (tid < 64) sB[tid] = bias[tid];

    #pragma unroll
    for (int i = tid; i < 2048; i += 256) {
        int r = i >> 5, q = i & 31;
        int row = rowBase + r;
        float4 v = make_float4(0.f, 0.f, 0.f, 0.f);
        if (row < nRows) {
            if (q < 16) v = reinterpret_cast<const float4*>(g_S)[row * 16 + q];
            else        v = reinterpret_cast<const float4*>(X)[row * 16 + (q - 16)];
        }
        sIn[r][q] = v;
    }
    __syncthreads();

    int tx = tid & 15;
    int ty = tid >> 4;
    float acc[4][4];
    #pragma unroll
    for (int i = 0; i < 4; i++)
        #pragma unroll
        for (int j = 0; j < 4; j++) acc[i][j] = 0.f;

    #pragma unroll 8
    for (int k4 = 0; k4 < 32; ++k4) {
        float4 a0 = sIn[ty      ][k4];
        float4 a1 = sIn[ty + 16][k4];
        float4 a2 = sIn[ty + 32][k4];
        float4 a3 = sIn[ty + 48][k4];
        float4 w0 = sW[4 * k4 + 0][tx];
        float4 w1 = sW[4 * k4 + 1][tx];
        float4 w2 = sW[4 * k4 + 2][tx];
        float4 w3 = sW[4 * k4 + 3][tx];
        float4 a[4] = {a0, a1, a2, a3};
        #pragma unroll
        for (int i = 0; i < 4; i++) {
            acc[i][0] += a[i].x * w0.x + a[i].y * w1.x + a[i].z * w2.x + a[i].w * w3.x;
            acc[i][1] += a[i].x * w0.y + a[i].y * w1.y + a[i].z * w2.y + a[i].w * w3.y;
            acc[i][2] += a[i].x * w0.z + a[i].y * w1.z + a[i].z * w2.z + a[i].w * w3.z;
            acc[i][3] += a[i].x * w0.w + a[i].y * w1.w + a[i].z * w2.w + a[i].w * w3.w;
        }
    }

    #pragma unroll
    for (int i = 0; i < 4; i++) {
        int row = rowBase + ty + 16 * i;
        if (row < nRows) {
            float4 o;
            o.x = fmaxf(acc[i][0] + sB[tx * 4 + 0], 0.f);
            o.y = fmaxf(acc[i][1] + sB[tx * 4 + 1], 0.f);
            o.z = fmaxf(acc[i][2] + sB[tx * 4 + 2], 0.f);
            o.w = fmaxf(acc[i][3] + sB[tx * 4 + 3], 0.f);
            reinterpret_cast<float4*>(g_h)[row * 16 + tx] = o;
        }
    }
}

// ---------------- global mean pool ----------------
__device__ __forceinline__ long long batch_at(const void* b, int i, int is64) {
    return is64 ? ((const long long*)b)[i] : (long long)((const int*)b)[i];
}

__global__ void pool_kernel(const void* __restrict__ batch, int nRows) {
    int g = blockIdx.x;
    int is64 = g_b64;
    int lo = 0, hi = nRows;
    while (lo < hi) { int m = (lo + hi) >> 1; if (batch_at(batch, m, is64) < g) lo = m + 1; else hi = m; }
    int start = lo;
    lo = 0; hi = nRows;
    while (lo < hi) { int m = (lo + hi) >> 1; if (batch_at(batch, m, is64) < g + 1) lo = m + 1; else hi = m; }
    int end = lo;

    int feat = threadIdx.x & 63;
    int rl   = threadIdx.x >> 6;
    float s = 0.f;
    for (int r = start + rl; r < end; r += 4)
        s += g_h[(long long)r * FEAT + feat];

    __shared__ float sm[4][64];
    sm[rl][feat] = s;
    __syncthreads();
    if (rl == 0) {
        float tot = sm[0][feat] + sm[1][feat] + sm[2][feat] + sm[3][feat];
        g_pooled[g * FEAT + feat] = tot / fmaxf((float)(end - start), 1.0f);
    }
}

// ---------------- heads ----------------
__global__ void head_kernel(const float* __restrict__ Wh, const float* __restrict__ bh,
                            const float* __restrict__ Wc, const float* __restrict__ bc,
                            const float* __restrict__ Wo, const float* __restrict__ bo,
                            float* __restrict__ out) {
    __shared__ float sp[64 * 64];
    __shared__ float sh[64 * 64];
    int tid = threadIdx.x;

    for (int i = tid; i < 4096; i += 256) sp[i] = g_pooled[i];
    __syncthreads();

    for (int i = tid; i < 4096; i += 256) {
        int g = i >> 6, j = i & 63;
        float ah = bh[j], ac = bc[j];
        #pragma unroll 8
        for (int k = 0; k < 64; k++) {
            float p = sp[g * 64 + k];
            ah += p * Wh[k * 64 + j];
            ac += p * Wc[k * 64 + j];
        }
        sh[i] = ah;
        out[2048 + i] = ah;
        out[2048 + 4096 + i] = ac;
    }
    __syncthreads();

    int warp = tid >> 5, lane = tid & 31;
    for (int g = warp; g < 64; g += 8) {
        float z = bo[lane];
        #pragma unroll 8
        for (int k = 0; k < 64; k++)
            z += sh[g * 64 + k] * Wo[k * 32 + lane];
        float m = z;
        #pragma unroll
        for (int off = 16; off > 0; off >>= 1)
            m = fmaxf(m, __shfl_xor_sync(0xffffffffu, m, off));
        float s = expf(z - m);
        #pragma unroll
        for (int off = 16; off > 0; off >>= 1)
            s += __shfl_xor_sync(0xffffffffu, s, off);
        out[g * 32 + lane] = z - m - logf(s);
    }
}

// ---------------- launch ----------------
extern "C" void kernel_launch(void* const* d_in, const int* in_sizes, int n_in,
                              void* d_out, int out_size) {
    const float* x     = (const float*)d_in[0];
    const void*  ei    = d_in[1];
    const void*  batch = d_in[2];
    const float* W1    = (const float*)d_in[3];
    const float* root1 = (const float*)d_in[4];
    const float* b1    = (const float*)d_in[5];
    const float* W2    = (const float*)d_in[6];
    const float* root2 = (const float*)d_in[7];
    const float* b2    = (const float*)d_in[8];
    const float* Wh    = (const float*)d_in[9];
    const float* bh    = (const float*)d_in[10];
    const float* Wc    = (const float*)d_in[11];
    const float* bc    = (const float*)d_in[12];
    const float* Wo    = (const float*)d_in[13];
    const float* bo    = (const float*)d_in[14];

    int nN = in_sizes[0] / FEAT;   // 100000
    int nE = in_sizes[1] / 2;      // 1600000

    int eBlocks = (nE + 255) / 256;
    int nBlocks = (nN + 255) / 256;
    int scanBlocks = (nN + 1023) / 1024;
    int gatherBlocks = (nN * 32 + 255) / 256;
    int gemmBlocks = (nN + 63) / 64;

    detect_kernel<<<1, 32>>>(ei, batch, nE, nN);

    // CSR build
    zero_deg_kernel<<<nBlocks, 256>>>(nN);
    hist_kernel<<<eBlocks, 256>>>(ei, nE);
    scan_block_kernel<<<scanBlocks, 256>>>(nN);
    scan_tops_kernel<<<1, 128>>>(scanBlocks);
    scan_add_kernel<<<nBlocks, 256>>>(nN, nE);
    fill_kernel<<<eBlocks, 256>>>(ei, nE);

    // layer 1
    gather_kernel<<<gatherBlocks, 256>>>(x, nN, 0);
    rgcn_gemm<<<gemmBlocks, 256>>>(x, W1, root1, b1, nN, 0);

    // layer 2
    gather_kernel<<<gatherBlocks, 256>>>(x, nN, 1);
    rgcn_gemm<<<gemmBlocks, 256>>>(x, W2, root2, b2, nN, 1);

    // pool + heads
    pool_kernel<<<N_GRAPHS, 256>>>(batch, nN);
    head_kernel<<<1, 256>>>(Wh, bh, Wc, bc, Wo, bo, (float*)d_out);
}